// round 15
// baseline (speedup 1.0000x reference)
#include <cuda_runtime.h>
#include <cuda_fp16.h>
#include <cstdint>
#include <cstddef>

#define B 8
#define L 2048
#define E 128
#define HP 136          // smem pitch in halves (272B, ldmatrix conflict-free)
#define P72 72          // smem pitch in halves (144B, trans-ldsm conflict-free)
#define LOG2E 1.4426950408889634f

// ---------------- scratch (device globals) ----------------------------------
__device__ half g_Sh[(size_t)B * L * L];      // fp16(exp(S*mask))            67 MB
__device__ half g_mkh[(size_t)L * L];         // fp16(mask * log2e)          8.4 MB
__device__ half g_Th[(size_t)B * E * L];      // fp16(G2 * 2^14 / d^2)      [e][j]
__device__ half g_Uqsh[(size_t)B * E * L];    // fp16(Uq^T * 2^10 / d)      [e][j]
__device__ half g_UidTh[(size_t)B * E * L];   // fp16(Uid^T)                [e][i]
__device__ half g_Uidwh[(size_t)B * L * E];   // fp16(Uid * wmul)           [i][e]
__device__ half g_Uqh[(size_t)B * L * E];     // fp16(Uq)                   [j][e]
__device__ float g_sid[B * L];
__device__ float g_sq[B * L];
__device__ float g_d[B * L];

#define SC_QI 0.0009765625f        // 2^-10
#define SC_TI 6.103515625e-05f     // 2^-14

// ---------------- helpers ----------------------------------------------------
__device__ __forceinline__ uint32_t smem_u32(const void* p) {
    uint32_t a;
    asm("{ .reg .u64 t; cvta.to.shared.u64 t, %1; cvt.u32.u64 %0, t; }"
        : "=r"(a) : "l"(p));
    return a;
}
__device__ __forceinline__ void ldsm4(uint32_t addr, uint32_t r[4]) {
    asm volatile("ldmatrix.sync.aligned.m8n8.x4.shared.b16 {%0,%1,%2,%3}, [%4];"
                 : "=r"(r[0]), "=r"(r[1]), "=r"(r[2]), "=r"(r[3]) : "r"(addr));
}
__device__ __forceinline__ void ldsm4t(uint32_t addr, uint32_t r[4]) {
    asm volatile("ldmatrix.sync.aligned.m8n8.x4.trans.shared.b16 {%0,%1,%2,%3}, [%4];"
                 : "=r"(r[0]), "=r"(r[1]), "=r"(r[2]), "=r"(r[3]) : "r"(addr));
}
__device__ __forceinline__ void mma16816(float c[4], const uint32_t a[4],
                                         uint32_t b0, uint32_t b1) {
    asm volatile(
        "mma.sync.aligned.m16n8k16.row.col.f32.f16.f16.f32 "
        "{%0,%1,%2,%3}, {%4,%5,%6,%7}, {%8,%9}, {%0,%1,%2,%3};"
        : "+f"(c[0]), "+f"(c[1]), "+f"(c[2]), "+f"(c[3])
        : "r"(a[0]), "r"(a[1]), "r"(a[2]), "r"(a[3]), "r"(b0), "r"(b1));
}
__device__ __forceinline__ half2 h2ex2(half2 x) {
    uint32_t r, xi = *(uint32_t*)&x;
    asm("ex2.approx.f16x2 %0, %1;" : "=r"(r) : "r"(xi));
    return *(half2*)&r;
}
__device__ __forceinline__ void cpa16(uint32_t dst, const void* src) {
    asm volatile("cp.async.cg.shared.global [%0], [%1], 16;"
                 :: "r"(dst), "l"(src) : "memory");
}
__device__ __forceinline__ void cpa_commit() {
    asm volatile("cp.async.commit_group;" ::: "memory");
}
__device__ __forceinline__ void cpa_wait1() {
    asm volatile("cp.async.wait_group 1;" ::: "memory");
}
__device__ __forceinline__ void cpa_wait0() {
    asm volatile("cp.async.wait_group 0;" ::: "memory");
}

// ---------------- kernel 1: row dots s_id, s_q + zero g_d -------------------
__global__ void k_dots(const float* __restrict__ Uq,
                       const float* __restrict__ Uid,
                       const float* __restrict__ Wc_w) {
    int r = blockIdx.x * 8 + threadIdx.y;
    int lane = threadIdx.x;
    float sid = 0.f, sq = 0.f;
#pragma unroll
    for (int t = 0; t < 4; t++) {
        int e = lane + t * 32;
        sid += Uid[(size_t)r * E + e] * Wc_w[e];
        sq  += Uq [(size_t)r * E + e] * Wc_w[E + e];
    }
#pragma unroll
    for (int o = 16; o; o >>= 1) {
        sid += __shfl_xor_sync(0xffffffffu, sid, o);
        sq  += __shfl_xor_sync(0xffffffffu, sq,  o);
    }
    if (lane == 0) { g_sid[r] = sid; g_sq[r] = sq; g_d[r] = 0.f; }
}

// ---------------- kernel 1b: fp16 operands + UidT transpose + mask slice ----
__global__ void k_prep(const float* __restrict__ Uq,
                       const float* __restrict__ Uid,
                       const float* __restrict__ Wc_w,
                       const float* __restrict__ mask) {
    __shared__ float tu[32][33];
    int l0 = blockIdx.x * 32, e0 = blockIdx.y * 32, b = blockIdx.z;
    int tx = threadIdx.x, ty = threadIdx.y;
    int tid = ty * 32 + tx;
    const float* ub = Uid + (size_t)b * L * E;
    const float* qb = Uq  + (size_t)b * L * E;
    float w = Wc_w[2 * E + e0 + tx];
#pragma unroll
    for (int r = 0; r < 4; r++) {
        int row = l0 + ty + r * 8;
        float u = ub[(size_t)row * E + e0 + tx];
        float q = qb[(size_t)row * E + e0 + tx];
        g_Uidwh[((size_t)b * L + row) * E + e0 + tx] = __float2half_rn(u * w);
        g_Uqh  [((size_t)b * L + row) * E + e0 + tx] = __float2half_rn(q);
        tu[ty + r * 8][tx] = u;
    }
    // fused mask conversion slice
    {
        int cid = blockIdx.x + (L / 32) * (blockIdx.y + (E / 32) * blockIdx.z);
        size_t i8 = ((size_t)cid * 256 + tid) * 8;
        float4 a = *(const float4*)&mask[i8];
        float4 c = *(const float4*)&mask[i8 + 4];
        *(half2*)&g_mkh[i8]     = __floats2half2_rn(a.x * LOG2E, a.y * LOG2E);
        *(half2*)&g_mkh[i8 + 2] = __floats2half2_rn(a.z * LOG2E, a.w * LOG2E);
        *(half2*)&g_mkh[i8 + 4] = __floats2half2_rn(c.x * LOG2E, c.y * LOG2E);
        *(half2*)&g_mkh[i8 + 6] = __floats2half2_rn(c.z * LOG2E, c.w * LOG2E);
    }
    __syncthreads();
#pragma unroll
    for (int r = 0; r < 4; r++) {
        int e = e0 + ty + r * 8;
        g_UidTh[((size_t)b * E + e) * L + l0 + tx] =
            __float2half_rn(tu[tx][ty + r * 8]);
    }
}

// ---------------- kernel 2: Sh = 2^(fp16(S*mask*log2e)) + column sums -------
__global__ __launch_bounds__(256, 2) void k_sgemm(const float* __restrict__ Wc_b) {
    extern __shared__ char smc[];
    half* Ah = (half*)smc;                       // [128][HP]
    half* Bh = Ah + 128 * HP;                    // [128][HP]
    half* Mh = Bh + 128 * HP;                    // [128][HP] mask tile
    float* red  = (float*)(Mh + 128 * HP);       // [128]
    float* sids = red + 128;                     // [128]
    float* sqbs = sids + 128;                    // [128] (sq + bias)
    half* stage = Ah;                            // reused post-mma
    int b  = blockIdx.z;
    int i0 = blockIdx.y * 128;
    int j0 = blockIdx.x * 128;
    int tid = threadIdx.x, lane = tid & 31, wid = tid >> 5;
    int wm = wid & 3, wn = wid >> 2;             // 4m x 2n warps, tile 32x64
    const half* A  = g_Uidwh + (size_t)b * L * E;
    const half* Bq = g_Uqh   + (size_t)b * L * E;
    uint32_t aB = smem_u32(Ah), bB = smem_u32(Bh), mB = smem_u32(Mh);

#pragma unroll
    for (int p = 0; p < 8; p++) {
        int idx = tid + p * 256;
        int row = idx >> 4, q = (idx & 15) * 8;
        cpa16(aB + (row * HP + q) * 2, A + (size_t)(i0 + row) * E + q);
    }
#pragma unroll
    for (int p = 0; p < 8; p++) {
        int idx = tid + p * 256;
        int row = idx >> 4, q = (idx & 15) * 8;
        cpa16(bB + (row * HP + q) * 2, Bq + (size_t)(j0 + row) * E + q);
    }
    cpa_commit();
#pragma unroll
    for (int p = 0; p < 8; p++) {
        int idx = tid + p * 256;
        int row = idx >> 4, q = (idx & 15) * 8;
        cpa16(mB + (row * HP + q) * 2, g_mkh + (size_t)(i0 + row) * L + j0 + q);
    }
    cpa_commit();
    if (tid < 128) {
        red[tid]  = 0.f;
        sids[tid] = g_sid[b * L + i0 + tid];
        sqbs[tid] = g_sq[b * L + j0 + tid] + *Wc_b;
    }
    cpa_wait1();            // A + B ready
    __syncthreads();

    float acc[2][8][4];
#pragma unroll
    for (int mi = 0; mi < 2; mi++)
#pragma unroll
        for (int nt = 0; nt < 8; nt++)
#pragma unroll
            for (int q = 0; q < 4; q++) acc[mi][nt][q] = 0.f;

#pragma unroll
    for (int kk = 0; kk < 8; kk++) {
        uint32_t a[2][4], bf[4][4];
#pragma unroll
        for (int mi = 0; mi < 2; mi++)
            ldsm4(aB + ((wm * 32 + mi * 16 + (lane & 15)) * HP + kk * 16 + (lane >> 4) * 8) * 2, a[mi]);
#pragma unroll
        for (int n4 = 0; n4 < 4; n4++)
            ldsm4(bB + ((wn * 64 + n4 * 16 + (lane & 15)) * HP + kk * 16 + (lane >> 4) * 8) * 2, bf[n4]);
#pragma unroll
        for (int n4 = 0; n4 < 4; n4++)
#pragma unroll
            for (int mi = 0; mi < 2; mi++) {
                mma16816(acc[mi][n4 * 2 + 0], a[mi], bf[n4][0], bf[n4][2]);
                mma16816(acc[mi][n4 * 2 + 1], a[mi], bf[n4][1], bf[n4][3]);
            }
    }
    cpa_wait0();            // mask tile ready
    __syncthreads();        // all ldsm done before stage overwrites Ah

    half2 csh[8];
#pragma unroll
    for (int nt = 0; nt < 8; nt++) csh[nt] = __floats2half2_rn(0.f, 0.f);
#pragma unroll
    for (int mi = 0; mi < 2; mi++) {
        int r0l = wm * 32 + mi * 16 + (lane >> 2);
        float sidv0 = sids[r0l];
        float sidv1 = sids[r0l + 8];
#pragma unroll
        for (int nt = 0; nt < 8; nt++) {
            int nl = wn * 64 + nt * 8 + (lane & 3) * 2;
            float2 sqb = *(const float2*)&sqbs[nl];
            float c0 = sidv0 + sqb.x, c1 = sidv0 + sqb.y;
            float c2 = sidv1 + sqb.x, c3 = sidv1 + sqb.y;
            float2 mk0 = __half22float2(*(const half2*)&Mh[r0l * HP + nl]);
            float2 mk1 = __half22float2(*(const half2*)&Mh[(r0l + 8) * HP + nl]);
            float t0 = (acc[mi][nt][0] + c0) * mk0.x;
            float t1 = (acc[mi][nt][1] + c1) * mk0.y;
            float t2 = (acc[mi][nt][2] + c2) * mk1.x;
            float t3 = (acc[mi][nt][3] + c3) * mk1.y;
            half2 h01 = h2ex2(__floats2half2_rn(t0, t1));
            half2 h23 = h2ex2(__floats2half2_rn(t2, t3));
            *(half2*)&stage[r0l * HP + nl]       = h01;
            *(half2*)&stage[(r0l + 8) * HP + nl] = h23;
            csh[nt] = __hadd2(csh[nt], __hadd2(h01, h23));
        }
    }
    float cs0[8], cs1[8];
#pragma unroll
    for (int nt = 0; nt < 8; nt++) {
        float2 c = __half22float2(csh[nt]);
        cs0[nt] = c.x; cs1[nt] = c.y;
    }
#pragma unroll
    for (int o = 16; o >= 4; o >>= 1)
#pragma unroll
        for (int nt = 0; nt < 8; nt++) {
            cs0[nt] += __shfl_xor_sync(0xffffffffu, cs0[nt], o);
            cs1[nt] += __shfl_xor_sync(0xffffffffu, cs1[nt], o);
        }
    if ((lane >> 2) == 0) {
#pragma unroll
        for (int nt = 0; nt < 8; nt++) {
            int nl = wn * 64 + nt * 8 + (lane & 3) * 2;
            atomicAdd(&red[nl], cs0[nt]);
            atomicAdd(&red[nl + 1], cs1[nt]);
        }
    }
    __syncthreads();   // stage + red complete

    half* Sout = g_Sh + (size_t)b * L * L;
#pragma unroll
    for (int p = 0; p < 8; p++) {
        int idx = tid + p * 256;
        int row = idx >> 4, q = (idx & 15) * 8;
        *(float4*)&Sout[(size_t)(i0 + row) * L + j0 + q] =
            *(const float4*)&stage[row * HP + q];
    }
    if (tid < 128) atomicAdd(&g_d[(size_t)b * L + j0 + tid], red[tid]);
}

// ---------------- kernel 5: Th = fp16((UidTh @ Sh) * 2^14 / d^2) ------------
// CTA 128e x 64j, 256 threads, KC=128, 2-stage; grid 256 -> all SMs,
// smem 106.5KB + launch_bounds(256,2) -> 2 CTAs/SM.  Fused Uqsh epilogue.
__global__ __launch_bounds__(256, 2) void k_tgemm2(const float* __restrict__ Uq) {
    extern __shared__ char smc[];
    half* As = (half*)smc;                 // [2][128][HP]  (e rows, k cols)
    half* Bs = As + 2 * 128 * HP;          // [2][128][P72] (k rows, j cols)
    const int stA = 128 * HP, stB = 128 * P72;
    int tid = threadIdx.x, lane = tid & 31, wid = tid >> 5;
    int wm = wid & 3, wn = wid >> 2;       // 4m x 2n, warp tile 32e x 32j
    int b = blockIdx.y;
    int j0 = blockIdx.x * 64;
    const half* Ab = g_UidTh + (size_t)b * E * L;
    const half* Sb = g_Sh + (size_t)b * L * L;
    uint32_t aB = smem_u32(As), bB = smem_u32(Bs);

    auto load = [&](int t) {
        int k0 = t * 128, s = t & 1;
#pragma unroll
        for (int p = 0; p < 8; p++) {
            int idx = tid + p * 256;
            int row = idx >> 4, q = (idx & 15) * 8;
            cpa16(aB + (s * stA + row * HP + q) * 2, Ab + (size_t)row * L + k0 + q);
        }
#pragma unroll
        for (int p = 0; p < 4; p++) {
            int idx = tid + p * 256;
            int row = idx >> 3, q = (idx & 7) * 8;
            cpa16(bB + (s * stB + row * P72 + q) * 2,
                  Sb + (size_t)(k0 + row) * L + j0 + q);
        }
        cpa_commit();
    };

    float acc[2][4][4];
#pragma unroll
    for (int mi = 0; mi < 2; mi++)
#pragma unroll
        for (int nt = 0; nt < 4; nt++)
#pragma unroll
            for (int q = 0; q < 4; q++) acc[mi][nt][q] = 0.f;

    const int iters = L / 128;
    load(0); load(1);
    for (int t = 0; t < iters; t++) {
        int s = t & 1;
        if (t + 1 < iters) cpa_wait1(); else cpa_wait0();
        __syncthreads();
#pragma unroll
        for (int kk = 0; kk < 8; kk++) {
            uint32_t a[2][4], bf[2][4];
#pragma unroll
            for (int mi = 0; mi < 2; mi++)
                ldsm4(aB + (s * stA + (wm * 32 + mi * 16 + (lane & 15)) * HP + kk * 16 + (lane >> 4) * 8) * 2, a[mi]);
#pragma unroll
            for (int n4 = 0; n4 < 2; n4++)
                ldsm4t(bB + (s * stB + (kk * 16 + (lane & 15)) * P72 + wn * 32 + n4 * 16 + (lane >> 4) * 8) * 2, bf[n4]);
#pragma unroll
            for (int n4 = 0; n4 < 2; n4++)
#pragma unroll
                for (int mi = 0; mi < 2; mi++) {
                    mma16816(acc[mi][n4 * 2 + 0], a[mi], bf[n4][0], bf[n4][1]);
                    mma16816(acc[mi][n4 * 2 + 1], a[mi], bf[n4][2], bf[n4][3]);
                }
        }
        __syncthreads();
        if (t + 2 < iters) load(t + 2);
    }

#pragma unroll
    for (int mi = 0; mi < 2; mi++) {
        int e0r = wm * 32 + mi * 16 + (lane >> 2);
#pragma unroll
        for (int nt = 0; nt < 4; nt++) {
            int j = j0 + wn * 32 + nt * 8 + (lane & 3) * 2;
            float2 dv = *(const float2*)&g_d[b * L + j];
            float s0 = __fdividef(16384.0f, dv.x * dv.x);
            float s1 = __fdividef(16384.0f, dv.y * dv.y);
            *(half2*)&g_Th[((size_t)b * E + e0r) * L + j] =
                __floats2half2_rn(acc[mi][nt][0] * s0, acc[mi][nt][1] * s1);
            *(half2*)&g_Th[((size_t)b * E + e0r + 8) * L + j] =
                __floats2half2_rn(acc[mi][nt][2] * s0, acc[mi][nt][3] * s1);
        }
    }

    // ---- fused Uqsh production: Uqsh[e][j0+j] = Uq[j][e]*2^10/d[j] (64 j)
    __syncthreads();                       // mainloop smem now dead
    float* Ust  = (float*)smc;             // [64][133] floats = 34048 B
    float* invs = Ust + 64 * 133;          // [64]
    const float* Uqb = Uq + (size_t)b * L * E;
#pragma unroll
    for (int p = 0; p < 8; p++) {
        int idx = tid + p * 256;
        int row = idx >> 5, c4 = (idx & 31) * 4;
        float4 v = *(const float4*)&Uqb[(size_t)(j0 + row) * E + c4];
        Ust[row * 133 + c4]     = v.x;
        Ust[row * 133 + c4 + 1] = v.y;
        Ust[row * 133 + c4 + 2] = v.z;
        Ust[row * 133 + c4 + 3] = v.w;
    }
    if (tid < 64) invs[tid] = __fdividef(1024.0f, g_d[b * L + j0 + tid]);
    __syncthreads();
#pragma unroll
    for (int p = 0; p < 16; p++) {
        int idx = tid + p * 256;
        int e = idx >> 5, j2 = (idx & 31) * 2;
        float v0 = Ust[j2 * 133 + e] * invs[j2];
        float v1 = Ust[(j2 + 1) * 133 + e] * invs[j2 + 1];
        *(half2*)&g_Uqsh[((size_t)b * E + e) * L + j0 + j2] =
            __floats2half2_rn(v0, v1);
    }
}

// ---------------- kernel 6: [A_D2Q | A_Q2D] = Sh @ [Uqsh | Th]^T ------------
// CTA 128m x 256n, 512 threads, KC=128, 2-stage; Uid tile staged through
// dead mainloop smem for the concat epilogue.
__global__ __launch_bounds__(512, 1) void k_final(const float* __restrict__ Uid,
                                                  float* __restrict__ out) {
    extern __shared__ char smc[];
    half* As = (half*)smc;                 // [2][128][HP]
    half* Bs = As + 2 * 128 * HP;          // [2][256][HP]
    const int stA = 128 * HP, stB = 256 * HP;
    int tid = threadIdx.x, lane = tid & 31, wid = tid >> 5;
    int wm = wid & 3, wn = wid >> 2;       // 4m x 4n
    int b = blockIdx.y;
    int i0 = blockIdx.x * 128;
    const half* Sb  = g_Sh   + (size_t)b * L * L + (size_t)i0 * L;
    const half* B1g = g_Uqsh + (size_t)b * E * L;
    const half* B2g = g_Th   + (size_t)b * E * L;
    uint32_t aB = smem_u32(As), bB = smem_u32(Bs);

    auto load = [&](int t) {
        int k0 = t * 128, s = t & 1;
#pragma unroll
        for (int p = 0; p < 4; p++) {
            int idx = tid + p * 512;
            int row = idx >> 4, q = (idx & 15) * 8;
            cpa16(aB + (s * stA + row * HP + q) * 2, Sb + (size_t)row * L + k0 + q);
        }
#pragma unroll
        for (int p = 0; p < 8; p++) {
            int idx = tid + p * 512;
            int row = idx >> 4, q = (idx & 15) * 8;
            const half* src = row < 128 ? B1g + (size_t)row * L + k0 + q
                                        : B2g + (size_t)(row - 128) * L + k0 + q;
            cpa16(bB + (s * stB + row * HP + q) * 2, src);
        }
        cpa_commit();
    };

    float acc[2][8][4];
#pragma unroll
    for (int mi = 0; mi < 2; mi++)
#pragma unroll
        for (int nt = 0; nt < 8; nt++)
#pragma unroll
            for (int q = 0; q < 4; q++) acc[mi][nt][q] = 0.f;

    const int iters = L / 128;
    load(0); load(1);
    for (int t = 0; t < iters; t++) {
        int s = t & 1;
        if (t + 1 < iters) cpa_wait1(); else cpa_wait0();
        __syncthreads();
#pragma unroll
        for (int kk = 0; kk < 8; kk++) {
            uint32_t a[2][4], bf[4][4];
#pragma unroll
            for (int mi = 0; mi < 2; mi++)
                ldsm4(aB + (s * stA + (wm * 32 + mi * 16 + (lane & 15)) * HP + kk * 16 + (lane >> 4) * 8) * 2, a[mi]);
#pragma unroll
            for (int n4 = 0; n4 < 4; n4++)
                ldsm4(bB + (s * stB + (wn * 64 + n4 * 16 + (lane & 15)) * HP + kk * 16 + (lane >> 4) * 8) * 2, bf[n4]);
#pragma unroll
            for (int n4 = 0; n4 < 4; n4++)
#pragma unroll
                for (int mi = 0; mi < 2; mi++) {
                    mma16816(acc[mi][n4 * 2 + 0], a[mi], bf[n4][0], bf[n4][2]);
                    mma16816(acc[mi][n4 * 2 + 1], a[mi], bf[n4][1], bf[n4][3]);
                }
        }
        __syncthreads();
        if (t + 2 < iters) load(t + 2);
    }

    // ---- stage fp32 Uid tile into dead mainloop smem (coalesced) ----------
    float* Uf = (float*)smc;               // [128][132] floats = 67584 B
#pragma unroll
    for (int p = 0; p < 8; p++) {
        int idx = tid + p * 512;
        int row = idx >> 5, c4 = (idx & 31) * 4;
        float4 v = *(const float4*)&Uid[((size_t)b * L + i0 + row) * E + c4];
        Uf[row * 132 + c4]     = v.x;
        Uf[row * 132 + c4 + 1] = v.y;
        Uf[row * 132 + c4 + 2] = v.z;
        Uf[row * 132 + c4 + 3] = v.w;
    }
    __syncthreads();

    // epilogue: out row i: [Uid | A_D2Q | Uid*A_D2Q | Uid*A_Q2D]
#pragma unroll
    for (int mi = 0; mi < 2; mi++) {
        int r0l = wm * 32 + mi * 16 + (lane >> 2);
#pragma unroll
        for (int nt = 0; nt < 8; nt++) {
            int n = wn * 64 + nt * 8 + (lane & 3) * 2;   // 0..255
#pragma unroll
            for (int h = 0; h < 2; h++) {
                int rl = r0l + h * 8;
                int gi = i0 + rl;
                float v0 = acc[mi][nt][h * 2], v1 = acc[mi][nt][h * 2 + 1];
                float* orow = out + ((size_t)b * L + gi) * (4 * E);
                if (n < 128) {
                    v0 *= SC_QI; v1 *= SC_QI;
                    float2 u = *(const float2*)&Uf[rl * 132 + n];
                    *(float2*)&orow[128 + n] = make_float2(v0, v1);
                    *(float2*)&orow[256 + n] = make_float2(v0 * u.x, v1 * u.y);
                } else {
                    int m = n - 128;
                    v0 *= SC_TI; v1 *= SC_TI;
                    float2 u = *(const float2*)&Uf[rl * 132 + m];
                    *(float2*)&orow[384 + m] = make_float2(v0 * u.x, v1 * u.y);
                }
            }
        }
    }
    // Uid copy into slot 0 (from smem)
#pragma unroll
    for (int p = 0; p < 8; p++) {
        int idx = tid + p * 512;
        int row = idx >> 5, c = (idx & 31) * 4;
        int gi = i0 + row;
        *(float4*)&out[((size_t)b * L + gi) * (4 * E) + c] =
            *(const float4*)&Uf[row * 132 + c];
    }
}

// ---------------- launch ----------------------------------------------------
extern "C" void kernel_launch(void* const* d_in, const int* in_sizes, int n_in,
                              void* d_out, int out_size) {
    const float* Uq   = (const float*)d_in[0];
    const float* Uid  = (const float*)d_in[1];
    const float* mask = (const float*)d_in[2];
    const float* Wc_w = (const float*)d_in[3];
    const float* Wc_b = (const float*)d_in[4];
    float* out = (float*)d_out;

    const int SMEM_SG = 3 * 128 * HP * 2 + 3 * 128 * 4;        // 106496
    const int SMEM_TG = (2 * 128 * HP + 2 * 128 * P72) * 2;    // 106496
    const int SMEM_FI = 2 * (128 + 256) * HP * 2;              // 208896
    cudaFuncSetAttribute(k_sgemm,  cudaFuncAttributeMaxDynamicSharedMemorySize, SMEM_SG);
    cudaFuncSetAttribute(k_tgemm2, cudaFuncAttributeMaxDynamicSharedMemorySize, SMEM_TG);
    cudaFuncSetAttribute(k_final,  cudaFuncAttributeMaxDynamicSharedMemorySize, SMEM_FI);

    k_dots<<<(B * L) / 8, dim3(32, 8)>>>(Uq, Uid, Wc_w);
    k_prep<<<dim3(L / 32, E / 32, B), dim3(32, 8)>>>(Uq, Uid, Wc_w, mask);
    k_sgemm<<<dim3(L / 128, L / 128, B), 256, SMEM_SG>>>(Wc_b);
    k_tgemm2<<<dim3(L / 64, B), 256, SMEM_TG>>>(Uq);
    k_final<<<dim3(L / 128, B), 512, SMEM_FI>>>(Uid, out);
}

// round 16
// speedup vs baseline: 1.0317x; 1.0317x over previous
#include <cuda_runtime.h>
#include <cuda_fp16.h>
#include <cstdint>
#include <cstddef>

#define B 8
#define L 2048
#define E 128
#define BL (B * L)
#define HP 136          // smem pitch in halves (272B, ldmatrix conflict-free)
#define LOG2E 1.4426950408889634f

// ---------------- scratch (device globals) ----------------------------------
__device__ half g_Sh[(size_t)B * L * L];      // fp16(exp(S*mask))            67 MB
__device__ half g_mkh[(size_t)L * L];         // fp16(mask * log2e)          8.4 MB
__device__ half g_Th[(size_t)B * E * L];      // fp16(G2 * 2^14 / d^2)      [e][j]
__device__ half g_Uqsh[(size_t)B * E * L];    // fp16(Uq^T * 2^10 / d)      [e][j]
__device__ half g_UidTh[(size_t)B * E * L];   // fp16(Uid^T)                [e][i]
__device__ half g_Uidwh[(size_t)B * L * E];   // fp16(Uid * wmul)           [i][e]
__device__ half g_Uqh[(size_t)B * L * E];     // fp16(Uq)                   [j][e]
__device__ float g_sid4[(size_t)4 * BL];      // per-e-tile partial dots
__device__ float g_sq4[(size_t)4 * BL];
__device__ float g_d[BL];

#define SC_QI 0.0009765625f        // 2^-10
#define SC_TI 6.103515625e-05f     // 2^-14

// ---------------- helpers ----------------------------------------------------
__device__ __forceinline__ uint32_t smem_u32(const void* p) {
    uint32_t a;
    asm("{ .reg .u64 t; cvta.to.shared.u64 t, %1; cvt.u32.u64 %0, t; }"
        : "=r"(a) : "l"(p));
    return a;
}
__device__ __forceinline__ void ldsm4(uint32_t addr, uint32_t r[4]) {
    asm volatile("ldmatrix.sync.aligned.m8n8.x4.shared.b16 {%0,%1,%2,%3}, [%4];"
                 : "=r"(r[0]), "=r"(r[1]), "=r"(r[2]), "=r"(r[3]) : "r"(addr));
}
__device__ __forceinline__ void ldsm4t(uint32_t addr, uint32_t r[4]) {
    asm volatile("ldmatrix.sync.aligned.m8n8.x4.trans.shared.b16 {%0,%1,%2,%3}, [%4];"
                 : "=r"(r[0]), "=r"(r[1]), "=r"(r[2]), "=r"(r[3]) : "r"(addr));
}
__device__ __forceinline__ void mma16816(float c[4], const uint32_t a[4],
                                         uint32_t b0, uint32_t b1) {
    asm volatile(
        "mma.sync.aligned.m16n8k16.row.col.f32.f16.f16.f32 "
        "{%0,%1,%2,%3}, {%4,%5,%6,%7}, {%8,%9}, {%0,%1,%2,%3};"
        : "+f"(c[0]), "+f"(c[1]), "+f"(c[2]), "+f"(c[3])
        : "r"(a[0]), "r"(a[1]), "r"(a[2]), "r"(a[3]), "r"(b0), "r"(b1));
}
__device__ __forceinline__ half2 h2ex2(half2 x) {
    uint32_t r, xi = *(uint32_t*)&x;
    asm("ex2.approx.f16x2 %0, %1;" : "=r"(r) : "r"(xi));
    return *(half2*)&r;
}
__device__ __forceinline__ void cpa16(uint32_t dst, const void* src) {
    asm volatile("cp.async.cg.shared.global [%0], [%1], 16;"
                 :: "r"(dst), "l"(src) : "memory");
}
__device__ __forceinline__ void cpa_commit() {
    asm volatile("cp.async.commit_group;" ::: "memory");
}
__device__ __forceinline__ void cpa_wait2() {
    asm volatile("cp.async.wait_group 2;" ::: "memory");
}
__device__ __forceinline__ void cpa_wait1() {
    asm volatile("cp.async.wait_group 1;" ::: "memory");
}
__device__ __forceinline__ void cpa_wait0() {
    asm volatile("cp.async.wait_group 0;" ::: "memory");
}

// ---------------- kernel 1: fp16 operands + UidT + row dots + mask ----------
__global__ void k_prep(const float* __restrict__ Uq,
                       const float* __restrict__ Uid,
                       const float* __restrict__ Wc_w,
                       const float* __restrict__ mask) {
    __shared__ float tu[32][33];
    int l0 = blockIdx.x * 32, e0 = blockIdx.y * 32, b = blockIdx.z;
    int tx = threadIdx.x, ty = threadIdx.y;
    int tid = ty * 32 + tx;
    const float* ub = Uid + (size_t)b * L * E;
    const float* qb = Uq  + (size_t)b * L * E;
    float w    = Wc_w[2 * E + e0 + tx];
    float wid  = Wc_w[e0 + tx];
    float wq   = Wc_w[E + e0 + tx];
#pragma unroll
    for (int r = 0; r < 4; r++) {
        int row = l0 + ty + r * 8;
        float u = ub[(size_t)row * E + e0 + tx];
        float q = qb[(size_t)row * E + e0 + tx];
        g_Uidwh[((size_t)b * L + row) * E + e0 + tx] = __float2half_rn(u * w);
        g_Uqh  [((size_t)b * L + row) * E + e0 + tx] = __float2half_rn(q);
        tu[ty + r * 8][tx] = u;
        // partial row dots over this e-tile (warp = fixed row)
        float ps = u * wid, pq = q * wq;
#pragma unroll
        for (int o = 16; o; o >>= 1) {
            ps += __shfl_xor_sync(0xffffffffu, ps, o);
            pq += __shfl_xor_sync(0xffffffffu, pq, o);
        }
        if (tx == 0) {
            g_sid4[(size_t)blockIdx.y * BL + b * L + row] = ps;
            g_sq4 [(size_t)blockIdx.y * BL + b * L + row] = pq;
        }
    }
    if (blockIdx.y == 0 && ty == 0) g_d[b * L + l0 + tx] = 0.f;
    // fused mask conversion slice
    {
        int cid = blockIdx.x + (L / 32) * (blockIdx.y + (E / 32) * blockIdx.z);
        size_t i8 = ((size_t)cid * 256 + tid) * 8;
        float4 a = *(const float4*)&mask[i8];
        float4 c = *(const float4*)&mask[i8 + 4];
        *(half2*)&g_mkh[i8]     = __floats2half2_rn(a.x * LOG2E, a.y * LOG2E);
        *(half2*)&g_mkh[i8 + 2] = __floats2half2_rn(a.z * LOG2E, a.w * LOG2E);
        *(half2*)&g_mkh[i8 + 4] = __floats2half2_rn(c.x * LOG2E, c.y * LOG2E);
        *(half2*)&g_mkh[i8 + 6] = __floats2half2_rn(c.z * LOG2E, c.w * LOG2E);
    }
    __syncthreads();
#pragma unroll
    for (int r = 0; r < 4; r++) {
        int e = e0 + ty + r * 8;
        g_UidTh[((size_t)b * E + e) * L + l0 + tx] =
            __float2half_rn(tu[tx][ty + r * 8]);
    }
}

// ---------------- kernel 2: Sh = 2^(fp16(S*mask*log2e)) + column sums -------
__global__ __launch_bounds__(256, 2) void k_sgemm(const float* __restrict__ Wc_b) {
    extern __shared__ char smc[];
    half* Ah = (half*)smc;                       // [128][HP]
    half* Bh = Ah + 128 * HP;                    // [128][HP]
    half* Mh = Bh + 128 * HP;                    // [128][HP] mask tile
    float* red  = (float*)(Mh + 128 * HP);       // [128]
    float* sids = red + 128;                     // [128]
    float* sqbs = sids + 128;                    // [128] (sq + bias)
    half* stage = Ah;                            // reused post-mma
    int b  = blockIdx.z;
    int i0 = blockIdx.y * 128;
    int j0 = blockIdx.x * 128;
    int tid = threadIdx.x, lane = tid & 31, wid = tid >> 5;
    int wm = wid & 3, wn = wid >> 2;             // 4m x 2n warps, tile 32x64
    const half* A  = g_Uidwh + (size_t)b * L * E;
    const half* Bq = g_Uqh   + (size_t)b * L * E;
    uint32_t aB = smem_u32(Ah), bB = smem_u32(Bh), mB = smem_u32(Mh);

#pragma unroll
    for (int p = 0; p < 8; p++) {
        int idx = tid + p * 256;
        int row = idx >> 4, q = (idx & 15) * 8;
        cpa16(aB + (row * HP + q) * 2, A + (size_t)(i0 + row) * E + q);
    }
#pragma unroll
    for (int p = 0; p < 8; p++) {
        int idx = tid + p * 256;
        int row = idx >> 4, q = (idx & 15) * 8;
        cpa16(bB + (row * HP + q) * 2, Bq + (size_t)(j0 + row) * E + q);
    }
    cpa_commit();
#pragma unroll
    for (int p = 0; p < 8; p++) {
        int idx = tid + p * 256;
        int row = idx >> 4, q = (idx & 15) * 8;
        cpa16(mB + (row * HP + q) * 2, g_mkh + (size_t)(i0 + row) * L + j0 + q);
    }
    cpa_commit();
    if (tid < 128) {
        red[tid]  = 0.f;
        int ri = b * L + i0 + tid;
        sids[tid] = g_sid4[ri] + g_sid4[BL + ri] + g_sid4[2 * BL + ri] + g_sid4[3 * BL + ri];
        int rj = b * L + j0 + tid;
        sqbs[tid] = g_sq4[rj] + g_sq4[BL + rj] + g_sq4[2 * BL + rj] + g_sq4[3 * BL + rj] + *Wc_b;
    }
    cpa_wait1();            // A + B ready
    __syncthreads();

    float acc[2][8][4];
#pragma unroll
    for (int mi = 0; mi < 2; mi++)
#pragma unroll
        for (int nt = 0; nt < 8; nt++)
#pragma unroll
            for (int q = 0; q < 4; q++) acc[mi][nt][q] = 0.f;

#pragma unroll
    for (int kk = 0; kk < 8; kk++) {
        uint32_t a[2][4], bf[4][4];
#pragma unroll
        for (int mi = 0; mi < 2; mi++)
            ldsm4(aB + ((wm * 32 + mi * 16 + (lane & 15)) * HP + kk * 16 + (lane >> 4) * 8) * 2, a[mi]);
#pragma unroll
        for (int n4 = 0; n4 < 4; n4++)
            ldsm4(bB + ((wn * 64 + n4 * 16 + (lane & 15)) * HP + kk * 16 + (lane >> 4) * 8) * 2, bf[n4]);
#pragma unroll
        for (int n4 = 0; n4 < 4; n4++)
#pragma unroll
            for (int mi = 0; mi < 2; mi++) {
                mma16816(acc[mi][n4 * 2 + 0], a[mi], bf[n4][0], bf[n4][2]);
                mma16816(acc[mi][n4 * 2 + 1], a[mi], bf[n4][1], bf[n4][3]);
            }
    }
    cpa_wait0();            // mask tile ready
    __syncthreads();        // all ldsm done before stage overwrites Ah

    half2 csh[8];
#pragma unroll
    for (int nt = 0; nt < 8; nt++) csh[nt] = __floats2half2_rn(0.f, 0.f);
#pragma unroll
    for (int mi = 0; mi < 2; mi++) {
        int r0l = wm * 32 + mi * 16 + (lane >> 2);
        float sidv0 = sids[r0l];
        float sidv1 = sids[r0l + 8];
#pragma unroll
        for (int nt = 0; nt < 8; nt++) {
            int nl = wn * 64 + nt * 8 + (lane & 3) * 2;
            float2 sqb = *(const float2*)&sqbs[nl];
            float c0 = sidv0 + sqb.x, c1 = sidv0 + sqb.y;
            float c2 = sidv1 + sqb.x, c3 = sidv1 + sqb.y;
            float2 mk0 = __half22float2(*(const half2*)&Mh[r0l * HP + nl]);
            float2 mk1 = __half22float2(*(const half2*)&Mh[(r0l + 8) * HP + nl]);
            float t0 = (acc[mi][nt][0] + c0) * mk0.x;
            float t1 = (acc[mi][nt][1] + c1) * mk0.y;
            float t2 = (acc[mi][nt][2] + c2) * mk1.x;
            float t3 = (acc[mi][nt][3] + c3) * mk1.y;
            half2 h01 = h2ex2(__floats2half2_rn(t0, t1));
            half2 h23 = h2ex2(__floats2half2_rn(t2, t3));
            *(half2*)&stage[r0l * HP + nl]       = h01;
            *(half2*)&stage[(r0l + 8) * HP + nl] = h23;
            csh[nt] = __hadd2(csh[nt], __hadd2(h01, h23));
        }
    }
    float cs0[8], cs1[8];
#pragma unroll
    for (int nt = 0; nt < 8; nt++) {
        float2 c = __half22float2(csh[nt]);
        cs0[nt] = c.x; cs1[nt] = c.y;
    }
#pragma unroll
    for (int o = 16; o >= 4; o >>= 1)
#pragma unroll
        for (int nt = 0; nt < 8; nt++) {
            cs0[nt] += __shfl_xor_sync(0xffffffffu, cs0[nt], o);
            cs1[nt] += __shfl_xor_sync(0xffffffffu, cs1[nt], o);
        }
    if ((lane >> 2) == 0) {
#pragma unroll
        for (int nt = 0; nt < 8; nt++) {
            int nl = wn * 64 + nt * 8 + (lane & 3) * 2;
            atomicAdd(&red[nl], cs0[nt]);
            atomicAdd(&red[nl + 1], cs1[nt]);
        }
    }
    __syncthreads();   // stage + red complete

    half* Sout = g_Sh + (size_t)b * L * L;
#pragma unroll
    for (int p = 0; p < 8; p++) {
        int idx = tid + p * 256;
        int row = idx >> 4, q = (idx & 15) * 8;
        *(float4*)&Sout[(size_t)(i0 + row) * L + j0 + q] =
            *(const float4*)&stage[row * HP + q];
    }
    if (tid < 128) atomicAdd(&g_d[(size_t)b * L + j0 + tid], red[tid]);
}

// ---------------- kernel 5: Th = fp16((UidTh @ Sh) * 2^14 / d^2) ------------
// CTA 128e x 128j, 256 threads, KC=128, **3-stage** pipeline (prefetch issued
// before the wait).  Sh via ldmatrix.trans.  Fused Uqsh epilogue.
__global__ __launch_bounds__(256, 1) void k_tgemm2(const float* __restrict__ Uq) {
    extern __shared__ char smc[];
    half* As = (half*)smc;                 // [3][128][HP]  (e rows, i cols)
    half* Bs = As + 3 * 128 * HP;          // [3][128][HP]  (i rows, j cols)
    const int stA = 128 * HP, stB = 128 * HP;
    int tid = threadIdx.x, lane = tid & 31, wid = tid >> 5;
    int wm = wid & 3, wn = wid >> 2;       // 4m x 2n
    int b = blockIdx.y;
    int j0 = blockIdx.x * 128;
    const half* Ab = g_UidTh + (size_t)b * E * L;
    const half* Sb = g_Sh + (size_t)b * L * L;
    uint32_t aB = smem_u32(As), bB = smem_u32(Bs);

    auto load = [&](int t) {
        int k0 = t * 128, s = t % 3;
#pragma unroll
        for (int p = 0; p < 8; p++) {
            int idx = tid + p * 256;
            int row = idx >> 4, q = (idx & 15) * 8;
            cpa16(aB + (s * stA + row * HP + q) * 2, Ab + (size_t)row * L + k0 + q);
        }
#pragma unroll
        for (int p = 0; p < 8; p++) {
            int idx = tid + p * 256;
            int row = idx >> 4, q = (idx & 15) * 8;
            cpa16(bB + (s * stB + row * HP + q) * 2, Sb + (size_t)(k0 + row) * L + j0 + q);
        }
        cpa_commit();
    };

    float acc[2][8][4];
#pragma unroll
    for (int mi = 0; mi < 2; mi++)
#pragma unroll
        for (int nt = 0; nt < 8; nt++)
#pragma unroll
            for (int q = 0; q < 4; q++) acc[mi][nt][q] = 0.f;

    const int iters = L / 128;
    load(0); load(1);
    for (int t = 0; t < iters; t++) {
        int s = t % 3;
        if (t + 2 < iters) { load(t + 2); cpa_wait2(); }
        else if (t + 1 < iters) cpa_wait1();
        else cpa_wait0();
        __syncthreads();
#pragma unroll
        for (int kk = 0; kk < 8; kk++) {
            uint32_t a[2][4], bf[4][4];
#pragma unroll
            for (int mi = 0; mi < 2; mi++)
                ldsm4(aB + (s * stA + (wm * 32 + mi * 16 + (lane & 15)) * HP + kk * 16 + (lane >> 4) * 8) * 2, a[mi]);
#pragma unroll
            for (int n4 = 0; n4 < 4; n4++)
                ldsm4t(bB + (s * stB + (kk * 16 + (lane & 15)) * HP + wn * 64 + n4 * 16 + (lane >> 4) * 8) * 2, bf[n4]);
#pragma unroll
            for (int n4 = 0; n4 < 4; n4++)
#pragma unroll
                for (int mi = 0; mi < 2; mi++) {
                    mma16816(acc[mi][n4 * 2 + 0], a[mi], bf[n4][0], bf[n4][1]);
                    mma16816(acc[mi][n4 * 2 + 1], a[mi], bf[n4][2], bf[n4][3]);
                }
        }
        __syncthreads();
    }

#pragma unroll
    for (int mi = 0; mi < 2; mi++) {
        int e0r = wm * 32 + mi * 16 + (lane >> 2);
#pragma unroll
        for (int nt = 0; nt < 8; nt++) {
            int j = j0 + wn * 64 + nt * 8 + (lane & 3) * 2;
            float2 dv = *(const float2*)&g_d[b * L + j];
            float s0 = __fdividef(16384.0f, dv.x * dv.x);
            float s1 = __fdividef(16384.0f, dv.y * dv.y);
            *(half2*)&g_Th[((size_t)b * E + e0r) * L + j] =
                __floats2half2_rn(acc[mi][nt][0] * s0, acc[mi][nt][1] * s1);
            *(half2*)&g_Th[((size_t)b * E + e0r + 8) * L + j] =
                __floats2half2_rn(acc[mi][nt][2] * s0, acc[mi][nt][3] * s1);
        }
    }

    // ---- fused Uqsh production: Uqsh[e][j0+j] = Uq[j][e]*2^10/d[j]
    __syncthreads();                       // mainloop smem now dead
    float* Ust  = (float*)smc;             // [128][133] floats = 68096 B
    float* invs = Ust + 128 * 133;         // [128]
    const float* Uqb = Uq + (size_t)b * L * E;
#pragma unroll
    for (int p = 0; p < 16; p++) {
        int idx = tid + p * 256;
        int row = idx >> 5, c4 = (idx & 31) * 4;
        float4 v = *(const float4*)&Uqb[(size_t)(j0 + row) * E + c4];
        Ust[row * 133 + c4]     = v.x;
        Ust[row * 133 + c4 + 1] = v.y;
        Ust[row * 133 + c4 + 2] = v.z;
        Ust[row * 133 + c4 + 3] = v.w;
    }
    if (tid < 128) invs[tid] = __fdividef(1024.0f, g_d[b * L + j0 + tid]);
    __syncthreads();
#pragma unroll
    for (int p = 0; p < 32; p++) {
        int idx = tid + p * 256;
        int e = idx >> 6, j2 = (idx & 63) * 2;
        float v0 = Ust[j2 * 133 + e] * invs[j2];
        float v1 = Ust[(j2 + 1) * 133 + e] * invs[j2 + 1];
        *(half2*)&g_Uqsh[((size_t)b * E + e) * L + j0 + j2] =
            __floats2half2_rn(v0, v1);
    }
}

// ---------------- kernel 6: [A_D2Q | A_Q2D] = Sh @ [Uqsh | Th]^T ------------
// CTA 128m x 256n, 512 threads, KC=128, 2-stage; Uid tile staged through
// dead mainloop smem for the concat epilogue.
__global__ __launch_bounds__(512, 1) void k_final(const float* __restrict__ Uid,
                                                  float* __restrict__ out) {
    extern __shared__ char smc[];
    half* As = (half*)smc;                 // [2][128][HP]
    half* Bs = As + 2 * 128 * HP;          // [2][256][HP]
    const int stA = 128 * HP, stB = 256 * HP;
    int tid = threadIdx.x, lane = tid & 31, wid = tid >> 5;
    int wm = wid & 3, wn = wid >> 2;       // 4m x 4n
    int b = blockIdx.y;
    int i0 = blockIdx.x * 128;
    const half* Sb  = g_Sh   + (size_t)b * L * L + (size_t)i0 * L;
    const half* B1g = g_Uqsh + (size_t)b * E * L;
    const half* B2g = g_Th   + (size_t)b * E * L;
    uint32_t aB = smem_u32(As), bB = smem_u32(Bs);

    auto load = [&](int t) {
        int k0 = t * 128, s = t & 1;
#pragma unroll
        for (int p = 0; p < 4; p++) {
            int idx = tid + p * 512;
            int row = idx >> 4, q = (idx & 15) * 8;
            cpa16(aB + (s * stA + row * HP + q) * 2, Sb + (size_t)row * L + k0 + q);
        }
#pragma unroll
        for (int p = 0; p < 8; p++) {
            int idx = tid + p * 512;
            int row = idx >> 4, q = (idx & 15) * 8;
            const half* src = row < 128 ? B1g + (size_t)row * L + k0 + q
                                        : B2g + (size_t)(row - 128) * L + k0 + q;
            cpa16(bB + (s * stB + row * HP + q) * 2, src);
        }
        cpa_commit();
    };

    float acc[2][8][4];
#pragma unroll
    for (int mi = 0; mi < 2; mi++)
#pragma unroll
        for (int nt = 0; nt < 8; nt++)
#pragma unroll
            for (int q = 0; q < 4; q++) acc[mi][nt][q] = 0.f;

    const int iters = L / 128;
    load(0); load(1);
    for (int t = 0; t < iters; t++) {
        int s = t & 1;
        if (t + 1 < iters) cpa_wait1(); else cpa_wait0();
        __syncthreads();
#pragma unroll
        for (int kk = 0; kk < 8; kk++) {
            uint32_t a[2][4], bf[4][4];
#pragma unroll
            for (int mi = 0; mi < 2; mi++)
                ldsm4(aB + (s * stA + (wm * 32 + mi * 16 + (lane & 15)) * HP + kk * 16 + (lane >> 4) * 8) * 2, a[mi]);
#pragma unroll
            for (int n4 = 0; n4 < 4; n4++)
                ldsm4(bB + (s * stB + (wn * 64 + n4 * 16 + (lane & 15)) * HP + kk * 16 + (lane >> 4) * 8) * 2, bf[n4]);
#pragma unroll
            for (int n4 = 0; n4 < 4; n4++)
#pragma unroll
                for (int mi = 0; mi < 2; mi++) {
                    mma16816(acc[mi][n4 * 2 + 0], a[mi], bf[n4][0], bf[n4][2]);
                    mma16816(acc[mi][n4 * 2 + 1], a[mi], bf[n4][1], bf[n4][3]);
                }
        }
        __syncthreads();
        if (t + 2 < iters) load(t + 2);
    }

    // ---- stage fp32 Uid tile into dead mainloop smem (coalesced) ----------
    float* Uf = (float*)smc;               // [128][132] floats = 67584 B
#pragma unroll
    for (int p = 0; p < 8; p++) {
        int idx = tid + p * 512;
        int row = idx >> 5, c4 = (idx & 31) * 4;
        float4 v = *(const float4*)&Uid[((size_t)b * L + i0 + row) * E + c4];
        Uf[row * 132 + c4]     = v.x;
        Uf[row * 132 + c4 + 1] = v.y;
        Uf[row * 132 + c4 + 2] = v.z;
        Uf[row * 132 + c4 + 3] = v.w;
    }
    __syncthreads();

    // epilogue: out row i: [Uid | A_D2Q | Uid*A_D2Q | Uid*A_Q2D]
#pragma unroll
    for (int mi = 0; mi < 2; mi++) {
        int r0l = wm * 32 + mi * 16 + (lane >> 2);
#pragma unroll
        for (int nt = 0; nt < 8; nt++) {
            int n = wn * 64 + nt * 8 + (lane & 3) * 2;   // 0..255
#pragma unroll
            for (int h = 0; h < 2; h++) {
                int rl = r0l + h * 8;
                int gi = i0 + rl;
                float v0 = acc[mi][nt][h * 2], v1 = acc[mi][nt][h * 2 + 1];
                float* orow = out + ((size_t)b * L + gi) * (4 * E);
                if (n < 128) {
                    v0 *= SC_QI; v1 *= SC_QI;
                    float2 u = *(const float2*)&Uf[rl * 132 + n];
                    *(float2*)&orow[128 + n] = make_float2(v0, v1);
                    *(float2*)&orow[256 + n] = make_float2(v0 * u.x, v1 * u.y);
                } else {
                    int m = n - 128;
                    v0 *= SC_TI; v1 *= SC_TI;
                    float2 u = *(const float2*)&Uf[rl * 132 + m];
                    *(float2*)&orow[384 + m] = make_float2(v0 * u.x, v1 * u.y);
                }
            }
        }
    }
    // Uid copy into slot 0 (from smem)
#pragma unroll
    for (int p = 0; p < 8; p++) {
        int idx = tid + p * 512;
        int row = idx >> 5, c = (idx & 31) * 4;
        int gi = i0 + row;
        *(float4*)&out[((size_t)b * L + gi) * (4 * E) + c] =
            *(const float4*)&Uf[row * 132 + c];
    }
}

// ---------------- launch ----------------------------------------------------
extern "C" void kernel_launch(void* const* d_in, const int* in_sizes, int n_in,
                              void* d_out, int out_size) {
    const float* Uq   = (const float*)d_in[0];
    const float* Uid  = (const float*)d_in[1];
    const float* mask = (const float*)d_in[2];
    const float* Wc_w = (const float*)d_in[3];
    const float* Wc_b = (const float*)d_in[4];
    float* out = (float*)d_out;

    const int SMEM_SG = 3 * 128 * HP * 2 + 3 * 128 * 4;    // 106496
    const int SMEM_TG = 3 * 2 * 128 * HP * 2;              // 208896
    const int SMEM_FI = 2 * (128 + 256) * HP * 2;          // 208896
    cudaFuncSetAttribute(k_sgemm,  cudaFuncAttributeMaxDynamicSharedMemorySize, SMEM_SG);
    cudaFuncSetAttribute(k_tgemm2, cudaFuncAttributeMaxDynamicSharedMemorySize, SMEM_TG);
    cudaFuncSetAttribute(k_final,  cudaFuncAttributeMaxDynamicSharedMemorySize, SMEM_FI);

    k_prep<<<dim3(L / 32, E / 32, B), dim3(32, 8)>>>(Uq, Uid, Wc_w, mask);
    k_sgemm<<<dim3(L / 128, L / 128, B), 256, SMEM_SG>>>(Wc_b);
    k_tgemm2<<<dim3(L / 128, B), 256, SMEM_TG>>>(Uq);
    k_final<<<dim3(L / 128, B), 512, SMEM_FI>>>(Uid, out);
}